// round 1
// baseline (speedup 1.0000x reference)
#include <cuda_runtime.h>
#include <math.h>

// RenderNet volume-rendering composite.
// Shapes (from reference): B=1, C=32, Z=64, Y=256, X=256, N = Y*X = 65536 rays.
// feat  [C,Z,Y,X] f32   (B folded out)
// occ   [Z,Y,X]   f32
// z_dist[Z]       f32
// noise [N,Z]     f32
// out layout (tuple flattened): [0]=total_loss, [1 .. 1+C*N)=rgb_e,
//   [1+C*N .. 1+2C*N)=feat_e, [1+2C*N .. 1+2C*N+N)=acc_e
//
// One thread per ray n = y*X + x. Consecutive threads = consecutive x =>
// all feat/occ/output accesses coalesced (128B per warp per request).
// The z cumprod recurrence is serial per ray; the C=32 feature FMA loop is
// fully unrolled giving 32 independent LDGs per z step (high MLP).

#define RN_C 32
#define RN_MAXZ 64
#define RAW_NOISE_STD 0.1f
#define FAR_DIST 1e10f

__global__ void __launch_bounds__(256)
rendernet_kernel(const float* __restrict__ feat,
                 const float* __restrict__ occ,
                 const float* __restrict__ z_dist,
                 const float* __restrict__ noise,
                 float* __restrict__ out,
                 int Z, int N)
{
    __shared__ float s_dist[RN_MAXZ];
    int tid = threadIdx.x;
    if (tid < Z) {
        float d = (tid < Z - 1) ? (z_dist[tid + 1] - z_dist[tid]) : FAR_DIST;
        s_dist[tid] = d;
    }
    __syncthreads();

    int n = blockIdx.x * blockDim.x + tid;
    if (n >= N) return;

    float acc[RN_C];
#pragma unroll
    for (int c = 0; c < RN_C; ++c) acc[c] = 0.0f;

    const float* occp   = occ + n;
    const float* noisep = noise + (size_t)n * Z;
    const float* featp  = feat + n;
    const size_t ZN = (size_t)Z * (size_t)N;

    float trans = 1.0f;
    float wsum  = 0.0f;

    for (int z = 0; z < Z; ++z) {
        float o  = occp[(size_t)z * N];
        float nz = noisep[z];
        float raw = fmaf(nz, RAW_NOISE_STD, o);
        raw = fmaxf(raw, 0.0f);
        float alpha = 1.0f - expf(-raw * s_dist[z]);
        float w = alpha * trans;                 // alpha_z * prod_{j<z}(1-alpha_j+1e-10)
        trans *= (1.0f - alpha + 1e-10f);
        wsum += w;

        const float* fz = featp + (size_t)z * N;
#pragma unroll
        for (int c = 0; c < RN_C; ++c) {
            acc[c] = fmaf(w, fz[(size_t)c * ZN], acc[c]);
        }
    }

    // Outputs
    float* rgb = out + 1;
    float* fe  = out + 1 + (size_t)RN_C * N;
    float* am  = out + 1 + 2 * (size_t)RN_C * N;

#pragma unroll
    for (int c = 0; c < RN_C; ++c) {
        float f = acc[c];
        fe[(size_t)c * N + n]  = f;
        // sigmoid(f) - 0.5
        rgb[(size_t)c * N + n] = 1.0f / (1.0f + expf(-f)) - 0.5f;
    }
    am[n] = fminf(fmaxf(wsum, 0.0f), 1.0f);

    if (n == 0) out[0] = 0.0f;   // total_loss
}

extern "C" void kernel_launch(void* const* d_in, const int* in_sizes, int n_in,
                              void* d_out, int out_size)
{
    const float* feat   = (const float*)d_in[0];
    const float* occ    = (const float*)d_in[1];
    const float* z_dist = (const float*)d_in[2];
    const float* noise  = (const float*)d_in[3];
    float* out = (float*)d_out;

    int Z = in_sizes[2];              // 64
    int occN = in_sizes[1];           // Z*Y*X
    int N = occN / Z;                 // Y*X = 65536 rays

    int block = 256;
    int grid = (N + block - 1) / block;
    rendernet_kernel<<<grid, block>>>(feat, occ, z_dist, noise, out, Z, N);
}

// round 2
// speedup vs baseline: 1.1456x; 1.1456x over previous
#include <cuda_runtime.h>
#include <math.h>

// RenderNet volume-rendering composite — round 2.
// Shapes: B=1, C=32, Z=64, Y=256, X=256, N = 65536 rays.
// feat [C,Z,N] f32, occ [Z,N] f32, z_dist [Z], noise [N,Z] f32.
// out: [0]=loss, [1..1+CN)=rgb_e, [1+CN..1+2CN)=feat_e, [..+N)=acc_e
//
// Block = 256 threads owns RAYS=64 rays:
//  phase 0: all 256 threads cooperatively stage the block's noise tile
//           (contiguous 64*Z floats in gmem) into smem, transposed+padded.
//  phase 1: warps 0-1 (64 threads) run the serial alpha/trans recurrence,
//           one ray per thread, writing weights[z][ray] to smem and acc_e.
//  phase 2: all 8 warps composite features: thread (cg, r) accumulates
//           8 channels of ray r; feat loads coalesced + streaming (__ldcs).
// Grid = N/64 = 1024 CTAs -> ~7 resident CTAs/SM, ~55 warps/SM.

#define RN_C 32
#define RN_Z 64
#define RN_RAYS 64
#define RN_CPT 8            // channels per thread (4 channel groups)
#define RAW_NOISE_STD 0.1f
#define FAR_DIST 1e10f

__global__ void __launch_bounds__(256)
rendernet_fast(const float* __restrict__ feat,
               const float* __restrict__ occ,
               const float* __restrict__ z_dist,
               const float* __restrict__ noise,
               float* __restrict__ out,
               int N)
{
    __shared__ float s_noise[RN_Z * (RN_RAYS + 1)]; // [z][ray], pad 65 to kill conflicts
    __shared__ float s_w[RN_Z * RN_RAYS];           // [z][ray]
    __shared__ float s_dist[RN_Z];

    const int tid = threadIdx.x;
    const int n0  = blockIdx.x * RN_RAYS;

    if (tid < RN_Z) {
        s_dist[tid] = (tid < RN_Z - 1) ? (z_dist[tid + 1] - z_dist[tid]) : FAR_DIST;
    }

    // ---- phase 0: coalesced noise stage (contiguous 64*Z floats) ----
    {
        const float* np = noise + (size_t)n0 * RN_Z;
#pragma unroll
        for (int i = tid; i < RN_RAYS * RN_Z; i += 256) {
            int r = i >> 6;          // i / RN_Z
            int z = i & (RN_Z - 1);  // i % RN_Z
            s_noise[z * (RN_RAYS + 1) + r] = np[i];
        }
    }
    __syncthreads();

    const int cg = tid >> 6;        // 0..3
    const int r  = tid & (RN_RAYS - 1);
    const int n  = n0 + r;
    const size_t ZN = (size_t)RN_Z * (size_t)N;

    // ---- phase 1: weight recurrence, warps 0-1 only ----
    if (cg == 0) {
        float trans = 1.0f;
        float wsum  = 0.0f;
        const float* occp = occ + n;
#pragma unroll 8
        for (int z = 0; z < RN_Z; ++z) {
            float o   = occp[(size_t)z * N];
            float nz  = s_noise[z * (RN_RAYS + 1) + r];
            float raw = fmaxf(fmaf(nz, RAW_NOISE_STD, o), 0.0f);
            float alpha = 1.0f - expf(-raw * s_dist[z]);
            float w = alpha * trans;
            trans *= (1.0f - alpha + 1e-10f);
            wsum  += w;
            s_w[z * RN_RAYS + r] = w;
        }
        float* am = out + 1 + 2 * (size_t)RN_C * N;
        am[n] = fminf(fmaxf(wsum, 0.0f), 1.0f);
    }
    __syncthreads();

    // ---- phase 2: feature composite, 8 channels per thread ----
    const int c0 = cg * RN_CPT;
    float acc[RN_CPT];
#pragma unroll
    for (int c = 0; c < RN_CPT; ++c) acc[c] = 0.0f;

    const float* fbase = feat + (size_t)c0 * ZN + n;
    for (int z = 0; z < RN_Z; ++z) {
        float w = s_w[z * RN_RAYS + r];
        const float* fz = fbase + (size_t)z * N;
#pragma unroll
        for (int c = 0; c < RN_CPT; ++c) {
            acc[c] = fmaf(w, __ldcs(fz + (size_t)c * ZN), acc[c]);
        }
    }

    float* rgb = out + 1;
    float* fe  = out + 1 + (size_t)RN_C * N;
#pragma unroll
    for (int c = 0; c < RN_CPT; ++c) {
        float f = acc[c];
        size_t idx = (size_t)(c0 + c) * N + n;
        fe[idx]  = f;
        rgb[idx] = 1.0f / (1.0f + expf(-f)) - 0.5f;
    }

    if (blockIdx.x == 0 && tid == 0) out[0] = 0.0f;
}

// ---- generic fallback (any Z), one thread per ray (round-1 kernel) ----
__global__ void __launch_bounds__(256)
rendernet_generic(const float* __restrict__ feat,
                  const float* __restrict__ occ,
                  const float* __restrict__ z_dist,
                  const float* __restrict__ noise,
                  float* __restrict__ out,
                  int Z, int N)
{
    extern __shared__ float s_d[];
    int tid = threadIdx.x;
    if (tid < Z)
        s_d[tid] = (tid < Z - 1) ? (z_dist[tid + 1] - z_dist[tid]) : FAR_DIST;
    __syncthreads();

    int n = blockIdx.x * blockDim.x + tid;
    if (n >= N) return;

    float acc[RN_C];
#pragma unroll
    for (int c = 0; c < RN_C; ++c) acc[c] = 0.0f;

    const float* occp   = occ + n;
    const float* noisep = noise + (size_t)n * Z;
    const float* featp  = feat + n;
    const size_t ZN = (size_t)Z * (size_t)N;

    float trans = 1.0f, wsum = 0.0f;
    for (int z = 0; z < Z; ++z) {
        float raw = fmaxf(fmaf(noisep[z], RAW_NOISE_STD, occp[(size_t)z * N]), 0.0f);
        float alpha = 1.0f - expf(-raw * s_d[z]);
        float w = alpha * trans;
        trans *= (1.0f - alpha + 1e-10f);
        wsum += w;
        const float* fz = featp + (size_t)z * N;
#pragma unroll
        for (int c = 0; c < RN_C; ++c)
            acc[c] = fmaf(w, fz[(size_t)c * ZN], acc[c]);
    }
    float* rgb = out + 1;
    float* fe  = out + 1 + (size_t)RN_C * N;
    float* am  = out + 1 + 2 * (size_t)RN_C * N;
#pragma unroll
    for (int c = 0; c < RN_C; ++c) {
        float f = acc[c];
        fe[(size_t)c * N + n]  = f;
        rgb[(size_t)c * N + n] = 1.0f / (1.0f + expf(-f)) - 0.5f;
    }
    am[n] = fminf(fmaxf(wsum, 0.0f), 1.0f);
    if (n == 0) out[0] = 0.0f;
}

extern "C" void kernel_launch(void* const* d_in, const int* in_sizes, int n_in,
                              void* d_out, int out_size)
{
    const float* feat   = (const float*)d_in[0];
    const float* occ    = (const float*)d_in[1];
    const float* z_dist = (const float*)d_in[2];
    const float* noise  = (const float*)d_in[3];
    float* out = (float*)d_out;

    int Z = in_sizes[2];
    int N = in_sizes[1] / Z;

    if (Z == RN_Z && (N % RN_RAYS) == 0) {
        int grid = N / RN_RAYS;
        rendernet_fast<<<grid, 256>>>(feat, occ, z_dist, noise, out, N);
    } else {
        int block = 256;
        int grid = (N + block - 1) / block;
        rendernet_generic<<<grid, block, Z * sizeof(float)>>>(feat, occ, z_dist, noise, out, Z, N);
    }
}

// round 4
// speedup vs baseline: 1.2241x; 1.0685x over previous
#include <cuda_runtime.h>
#include <math.h>

// RenderNet volume-rendering composite — round 4 (= round 3 with scalar stores).
// Shapes: B=1, C=32, Z=64, Y=256, X=256, N=65536 rays.
// feat [C,Z,N] f32, occ [Z,N] f32, z_dist [Z], noise [N,Z] f32.
// out: [0]=loss, [1..1+CN)=rgb_e, [1+CN..1+2CN)=feat_e, [..+N)=acc_e
// NOTE: out+1 is only 4B-aligned -> output stores MUST be scalar (round-3
// float4 stores trapped with "misaligned address").
//
// Block = 256 threads owns 64 rays.
//  phase 1: threads 0-63 run the serial alpha/trans recurrence (one ray each),
//           noise row read as float4 (contiguous 256B per thread).
//  phase 2: thread (cgr, rg) accumulates channel pair {2cgr, 2cgr+1} for ray
//           quad [4rg, 4rg+4): two LDG.128 per z, z unrolled 4.

#define RN_C 32
#define RN_Z 64
#define RN_RAYS 64
#define RAW_NOISE_STD 0.1f
#define FAR_DIST 1e10f

__global__ void __launch_bounds__(256)
rendernet_v4(const float* __restrict__ feat,
             const float* __restrict__ occ,
             const float* __restrict__ z_dist,
             const float* __restrict__ noise,
             float* __restrict__ out,
             int N)
{
    __shared__ float s_w[RN_Z * RN_RAYS];   // [z][ray], 16KB
    __shared__ float s_dist[RN_Z];

    const int tid = threadIdx.x;
    const int n0  = blockIdx.x * RN_RAYS;

    if (tid < RN_Z) {
        s_dist[tid] = (tid < RN_Z - 1) ? (z_dist[tid + 1] - z_dist[tid]) : FAR_DIST;
    }
    __syncthreads();

    // ---- phase 1: weight recurrence, threads 0..63 (one ray each) ----
    if (tid < RN_RAYS) {
        const int r = tid;
        const int n = n0 + r;
        const float4* np4 = (const float4*)(noise + (size_t)n * RN_Z);
        const float* occp = occ + n;

        float trans = 1.0f;
        float wsum  = 0.0f;
#pragma unroll
        for (int zq = 0; zq < RN_Z / 4; ++zq) {
            float4 nz4 = __ldcs(np4 + zq);
            float nzv[4] = {nz4.x, nz4.y, nz4.z, nz4.w};
#pragma unroll
            for (int j = 0; j < 4; ++j) {
                int z = zq * 4 + j;
                float o   = occp[(size_t)z * N];
                float raw = fmaxf(fmaf(nzv[j], RAW_NOISE_STD, o), 0.0f);
                float alpha = 1.0f - expf(-raw * s_dist[z]);
                float w = alpha * trans;
                trans *= (1.0f - alpha + 1e-10f);
                wsum  += w;
                s_w[z * RN_RAYS + r] = w;
            }
        }
        float* am = out + 1 + 2 * (size_t)RN_C * N;
        am[n] = fminf(fmaxf(wsum, 0.0f), 1.0f);
    }
    __syncthreads();

    // ---- phase 2: feature composite ----
    const int rg  = tid & 15;        // ray quad index 0..15
    const int cgr = tid >> 4;        // channel pair index 0..15
    const int c0  = cgr * 2;
    const size_t ZN = (size_t)RN_Z * (size_t)N;

    const float* fbase = feat + (size_t)c0 * ZN + n0 + rg * 4;

    float4 a0 = {0.f, 0.f, 0.f, 0.f};
    float4 a1 = {0.f, 0.f, 0.f, 0.f};

#pragma unroll 4
    for (int z = 0; z < RN_Z; ++z) {
        float4 w  = *(const float4*)&s_w[z * RN_RAYS + rg * 4];
        const float* fz = fbase + (size_t)z * N;
        float4 v0 = __ldcs((const float4*)fz);
        float4 v1 = __ldcs((const float4*)(fz + ZN));
        a0.x = fmaf(w.x, v0.x, a0.x);
        a0.y = fmaf(w.y, v0.y, a0.y);
        a0.z = fmaf(w.z, v0.z, a0.z);
        a0.w = fmaf(w.w, v0.w, a0.w);
        a1.x = fmaf(w.x, v1.x, a1.x);
        a1.y = fmaf(w.y, v1.y, a1.y);
        a1.z = fmaf(w.z, v1.z, a1.z);
        a1.w = fmaf(w.w, v1.w, a1.w);
    }

    float* rgb = out + 1;
    float* fe  = out + 1 + (size_t)RN_C * N;
    const size_t o0 = (size_t)c0 * N + n0 + rg * 4;

    // scalar stores: out+1 is only 4B-aligned
    float av0[4] = {a0.x, a0.y, a0.z, a0.w};
    float av1[4] = {a1.x, a1.y, a1.z, a1.w};
#pragma unroll
    for (int j = 0; j < 4; ++j) {
        fe[o0 + j]      = av0[j];
        fe[o0 + N + j]  = av1[j];
        rgb[o0 + j]     = 1.0f / (1.0f + expf(-av0[j])) - 0.5f;
        rgb[o0 + N + j] = 1.0f / (1.0f + expf(-av1[j])) - 0.5f;
    }

    if (blockIdx.x == 0 && tid == 0) out[0] = 0.0f;
}

// ---- generic fallback (any Z/N), one thread per ray ----
__global__ void __launch_bounds__(256)
rendernet_generic(const float* __restrict__ feat,
                  const float* __restrict__ occ,
                  const float* __restrict__ z_dist,
                  const float* __restrict__ noise,
                  float* __restrict__ out,
                  int Z, int N)
{
    extern __shared__ float s_d[];
    int tid = threadIdx.x;
    if (tid < Z)
        s_d[tid] = (tid < Z - 1) ? (z_dist[tid + 1] - z_dist[tid]) : FAR_DIST;
    __syncthreads();

    int n = blockIdx.x * blockDim.x + tid;
    if (n >= N) return;

    float acc[RN_C];
#pragma unroll
    for (int c = 0; c < RN_C; ++c) acc[c] = 0.0f;

    const float* occp   = occ + n;
    const float* noisep = noise + (size_t)n * Z;
    const float* featp  = feat + n;
    const size_t ZN = (size_t)Z * (size_t)N;

    float trans = 1.0f, wsum = 0.0f;
    for (int z = 0; z < Z; ++z) {
        float raw = fmaxf(fmaf(noisep[z], RAW_NOISE_STD, occp[(size_t)z * N]), 0.0f);
        float alpha = 1.0f - expf(-raw * s_d[z]);
        float w = alpha * trans;
        trans *= (1.0f - alpha + 1e-10f);
        wsum += w;
        const float* fz = featp + (size_t)z * N;
#pragma unroll
        for (int c = 0; c < RN_C; ++c)
            acc[c] = fmaf(w, fz[(size_t)c * ZN], acc[c]);
    }
    float* rgb = out + 1;
    float* fe  = out + 1 + (size_t)RN_C * N;
    float* am  = out + 1 + 2 * (size_t)RN_C * N;
#pragma unroll
    for (int c = 0; c < RN_C; ++c) {
        float f = acc[c];
        fe[(size_t)c * N + n]  = f;
        rgb[(size_t)c * N + n] = 1.0f / (1.0f + expf(-f)) - 0.5f;
    }
    am[n] = fminf(fmaxf(wsum, 0.0f), 1.0f);
    if (n == 0) out[0] = 0.0f;
}

extern "C" void kernel_launch(void* const* d_in, const int* in_sizes, int n_in,
                              void* d_out, int out_size)
{
    const float* feat   = (const float*)d_in[0];
    const float* occ    = (const float*)d_in[1];
    const float* z_dist = (const float*)d_in[2];
    const float* noise  = (const float*)d_in[3];
    float* out = (float*)d_out;

    int Z = in_sizes[2];
    int N = in_sizes[1] / Z;

    if (Z == RN_Z && (N % RN_RAYS) == 0) {
        int grid = N / RN_RAYS;
        rendernet_v4<<<grid, 256>>>(feat, occ, z_dist, noise, out, N);
    } else {
        int block = 256;
        int grid = (N + block - 1) / block;
        rendernet_generic<<<grid, block, Z * sizeof(float)>>>(feat, occ, z_dist, noise, out, Z, N);
    }
}